// round 1
// baseline (speedup 1.0000x reference)
#include <cuda_runtime.h>
#include <cstdint>
#include <cstddef>

#define BB 131072

// ---------------- scratch (device globals: no runtime allocation) ----------------
__device__ float g_z[(size_t)BB * 64];
__device__ int   g_idx[BB];

// ---------------- threefry2x32 (exact JAX rounds) ----------------
__device__ __forceinline__ uint32_t rotl32(uint32_t x, int d) {
    return (x << d) | (x >> (32 - d));
}

__device__ __forceinline__ void threefry2x32(uint32_t k0, uint32_t k1,
                                             uint32_t x0, uint32_t x1,
                                             uint32_t& o0, uint32_t& o1) {
    uint32_t ks0 = k0, ks1 = k1, ks2 = 0x1BD11BDAu ^ k0 ^ k1;
    x0 += ks0; x1 += ks1;
    // i = 0 : rotations [13,15,26,6]
    x0 += x1; x1 = rotl32(x1, 13); x1 ^= x0;
    x0 += x1; x1 = rotl32(x1, 15); x1 ^= x0;
    x0 += x1; x1 = rotl32(x1, 26); x1 ^= x0;
    x0 += x1; x1 = rotl32(x1,  6); x1 ^= x0;
    x0 += ks1; x1 += ks2 + 1u;
    // i = 1 : rotations [17,29,16,24]
    x0 += x1; x1 = rotl32(x1, 17); x1 ^= x0;
    x0 += x1; x1 = rotl32(x1, 29); x1 ^= x0;
    x0 += x1; x1 = rotl32(x1, 16); x1 ^= x0;
    x0 += x1; x1 = rotl32(x1, 24); x1 ^= x0;
    x0 += ks2; x1 += ks0 + 2u;
    // i = 2 : rotations [13,15,26,6]
    x0 += x1; x1 = rotl32(x1, 13); x1 ^= x0;
    x0 += x1; x1 = rotl32(x1, 15); x1 ^= x0;
    x0 += x1; x1 = rotl32(x1, 26); x1 ^= x0;
    x0 += x1; x1 = rotl32(x1,  6); x1 ^= x0;
    x0 += ks0; x1 += ks1 + 3u;
    // i = 3 : rotations [17,29,16,24]
    x0 += x1; x1 = rotl32(x1, 17); x1 ^= x0;
    x0 += x1; x1 = rotl32(x1, 29); x1 ^= x0;
    x0 += x1; x1 = rotl32(x1, 16); x1 ^= x0;
    x0 += x1; x1 = rotl32(x1, 24); x1 ^= x0;
    x0 += ks1; x1 += ks2 + 4u;
    // i = 4 : rotations [13,15,26,6]
    x0 += x1; x1 = rotl32(x1, 13); x1 ^= x0;
    x0 += x1; x1 = rotl32(x1, 15); x1 ^= x0;
    x0 += x1; x1 = rotl32(x1, 26); x1 ^= x0;
    x0 += x1; x1 = rotl32(x1,  6); x1 ^= x0;
    x0 += ks2; x1 += ks0 + 5u;
    o0 = x0; o1 = x1;
}

// ---------------- Kernel A: encoder + policy softmax + categorical sample ----------------
__global__ __launch_bounds__(128) void enc_pol_kernel(
    const float* __restrict__ x, const float* __restrict__ enc_w,
    const float* __restrict__ enc_b, const float* __restrict__ pol_w,
    const float* __restrict__ pol_b, float* __restrict__ probs_out) {
    int b = blockIdx.x * 128 + threadIdx.x;

    float xv[5];
#pragma unroll
    for (int d = 0; d < 5; ++d) xv[d] = x[b * 5 + d];

    float z[64];
#pragma unroll
    for (int j = 0; j < 64; ++j) {
        float a = enc_b[j];
#pragma unroll
        for (int d = 0; d < 5; ++d) a = fmaf(xv[d], enc_w[j * 5 + d], a);
        z[j] = tanhf(a);
    }
    // store z (vectorized)
    float4* zo = (float4*)(g_z + (size_t)b * 64);
#pragma unroll
    for (int j = 0; j < 16; ++j)
        zo[j] = make_float4(z[4 * j], z[4 * j + 1], z[4 * j + 2], z[4 * j + 3]);

    // policy logits + max
    float l[40];
    float m = -3.402823466e38f;
#pragma unroll 4
    for (int k = 0; k < 40; ++k) {
        float a = pol_b[k];
#pragma unroll
        for (int d = 0; d < 64; ++d) a = fmaf(z[d], pol_w[k * 64 + d], a);
        l[k] = a;
        m = fmaxf(m, a);
    }
    // softmax (jax.nn.softmax form: exp(x-max)/sum)
    float sum = 0.f;
#pragma unroll 4
    for (int k = 0; k < 40; ++k) {
        float e = expf(l[k] - m);
        l[k] = e;
        sum += e;
    }
    // gumbel-argmax sampling, partitionable threefry with key (0,1)
    int best = 0;
    float bestv = -3.402823466e38f;
    const float TINY = 1.17549435e-38f;
#pragma unroll 4
    for (int k = 0; k < 40; ++k) {
        float p = l[k] / sum;
        l[k] = p;
        uint32_t i = (uint32_t)(b * 40 + k);  // 64-bit linear index; hi word = 0
        uint32_t o0, o1;
        threefry2x32(0u, 1u, 0u, i, o0, o1);
        uint32_t bits = o0 ^ o1;
        float f = __uint_as_float((bits >> 9) | 0x3f800000u) - 1.0f;
        float u = fmaxf(f * (1.0f - TINY) + TINY, TINY);
        float g = -logf(-logf(u));
        float v = logf(p) + g;
        if (v > bestv) { bestv = v; best = k; }
    }
    g_idx[b] = best;

    float4* po = (float4*)(probs_out + (size_t)b * 40);
#pragma unroll
    for (int j = 0; j < 10; ++j)
        po[j] = make_float4(l[4 * j], l[4 * j + 1], l[4 * j + 2], l[4 * j + 3]);
}

// ---------------- Kernel B: TRIZ expert bank (f32x2 packed FMA) ----------------
// Block = (expert k, 256-row tile). z tile transposed in smem [d][row] (pair-loadable),
// weights pre-duplicated as f32x2 [d][o] in smem. Thread tile: 16 rows (8 pairs) x 4
// strided columns {cg, cg+16, cg+32, cg+48} -> conflict-free LDS.64 of weights.
#define ZS 258  // padded row stride for transposed z (even for 8B loads, %32 != 0)
#define TRIZ_SMEM_BYTES (64 * ZS * 4 + 64 * 64 * 8 + 64 * 4)

__device__ __forceinline__ void fma2(unsigned long long& acc,
                                     unsigned long long a, unsigned long long b) {
    asm("fma.rn.f32x2 %0, %1, %2, %0;" : "+l"(acc) : "l"(a), "l"(b));
}

__global__ __launch_bounds__(256) void triz_kernel(
    const float* __restrict__ triz_w, const float* __restrict__ triz_b,
    float* __restrict__ h_out) {
    extern __shared__ float smem[];
    float*  zs = smem;                          // [64][ZS]
    float2* w2 = (float2*)(smem + 64 * ZS);     // [64][64], each value duplicated
    float*  bs = (float*)(w2 + 64 * 64);        // [64]

    int k = blockIdx.x;                   // expert
    size_t row0 = (size_t)blockIdx.y * 256;
    int t = threadIdx.x;

    // load z tile transposed: g_z[row][d] -> zs[d][row]
    const float* zg = g_z + row0 * 64;
#pragma unroll
    for (int i = 0; i < 64; ++i) {
        int idx = t + i * 256;            // idx = r*64 + d
        zs[(idx & 63) * ZS + (idx >> 6)] = zg[idx];
    }
    // load weights transposed + duplicated: triz_w[k][o][d] -> w2[d][o] = {w,w}
    const float* wg = triz_w + k * 4096;
#pragma unroll
    for (int i = 0; i < 16; ++i) {
        int idx = t + i * 256;            // idx = o*64 + d
        float w = wg[idx];
        w2[(idx & 63) * 64 + (idx >> 6)] = make_float2(w, w);
    }
    if (t < 64) bs[t] = triz_b[k * 64 + t];
    __syncthreads();

    int cg = t & 15;                      // column within group of 16
    int r0 = (t >> 4) * 16;               // 16 rows per thread

    unsigned long long acc[8][4];
#pragma unroll
    for (int i = 0; i < 8; ++i)
#pragma unroll
        for (int j = 0; j < 4; ++j) acc[i][j] = 0ull;

#pragma unroll 4
    for (int d = 0; d < 64; ++d) {
        unsigned long long zz[8], ww[4];
        const float* zp = zs + d * ZS + r0;
#pragma unroll
        for (int i = 0; i < 8; ++i)
            zz[i] = *(const unsigned long long*)(zp + 2 * i);
        const float2* wp = w2 + d * 64 + cg;
#pragma unroll
        for (int j = 0; j < 4; ++j)
            ww[j] = *(const unsigned long long*)(wp + 16 * j);
#pragma unroll
        for (int i = 0; i < 8; ++i)
#pragma unroll
            for (int j = 0; j < 4; ++j) fma2(acc[i][j], zz[i], ww[j]);
    }

    // bias + relu + store h[b][k][c]
#pragma unroll
    for (int j = 0; j < 4; ++j) {
        int c = cg + 16 * j;
        float bias = bs[c];
#pragma unroll
        for (int i = 0; i < 8; ++i) {
            float lo = __uint_as_float((uint32_t)acc[i][j]);
            float hi = __uint_as_float((uint32_t)(acc[i][j] >> 32));
            size_t r = row0 + r0 + 2 * i;
            h_out[r * 2560 + k * 64 + c]       = fmaxf(lo + bias, 0.f);
            h_out[(r + 1) * 2560 + k * 64 + c] = fmaxf(hi + bias, 0.f);
        }
    }
}

// ---------------- Kernel C: gather selected expert + decoder ----------------
__global__ __launch_bounds__(256) void decode_kernel(
    const float* __restrict__ dec_w, const float* __restrict__ dec_b,
    const float* __restrict__ h, float* __restrict__ out) {
    int b = blockIdx.x * 256 + threadIdx.x;
    int k = g_idx[b];
    const float4* hp = (const float4*)(h + ((size_t)b * 40 + k) * 64);
    float acc[5];
#pragma unroll
    for (int j = 0; j < 5; ++j) acc[j] = dec_b[j];
#pragma unroll
    for (int i = 0; i < 16; ++i) {
        float4 v = hp[i];
        int d = i * 4;
#pragma unroll
        for (int j = 0; j < 5; ++j) {
            acc[j] = fmaf(v.x, dec_w[j * 64 + d],     acc[j]);
            acc[j] = fmaf(v.y, dec_w[j * 64 + d + 1], acc[j]);
            acc[j] = fmaf(v.z, dec_w[j * 64 + d + 2], acc[j]);
            acc[j] = fmaf(v.w, dec_w[j * 64 + d + 3], acc[j]);
        }
    }
#pragma unroll
    for (int j = 0; j < 5; ++j) out[b * 5 + j] = acc[j];
}

// ---------------- launch ----------------
extern "C" void kernel_launch(void* const* d_in, const int* in_sizes, int n_in,
                              void* d_out, int out_size) {
    const float* x      = (const float*)d_in[0];
    const float* enc_w  = (const float*)d_in[1];
    const float* enc_b  = (const float*)d_in[2];
    const float* triz_w = (const float*)d_in[3];
    const float* triz_b = (const float*)d_in[4];
    const float* pol_w  = (const float*)d_in[5];
    const float* pol_b  = (const float*)d_in[6];
    const float* dec_w  = (const float*)d_in[7];
    const float* dec_b  = (const float*)d_in[8];

    float* out   = (float*)d_out;                 // [B,5]
    float* probs = out + (size_t)BB * 5;          // [B,40]
    float* h     = out + (size_t)BB * 45;         // [B,40,64]

    cudaFuncSetAttribute(triz_kernel, cudaFuncAttributeMaxDynamicSharedMemorySize,
                         TRIZ_SMEM_BYTES);

    enc_pol_kernel<<<BB / 128, 128>>>(x, enc_w, enc_b, pol_w, pol_b, probs);
    triz_kernel<<<dim3(40, BB / 256), 256, TRIZ_SMEM_BYTES>>>(triz_w, triz_b, h);
    decode_kernel<<<BB / 256, 256>>>(dec_w, dec_b, h, out);
}

// round 6
// speedup vs baseline: 2.4051x; 2.4051x over previous
#include <cuda_runtime.h>
#include <cuda_bf16.h>
#include <cstdint>
#include <cstddef>

#define BB 131072

// ---------------- scratch (device globals) ----------------
__device__ __nv_bfloat16 g_zhi[(size_t)BB * 64];
__device__ __nv_bfloat16 g_zlo[(size_t)BB * 64];
__device__ __nv_bfloat16 g_whi[40 * 4096];
__device__ __nv_bfloat16 g_wlo[40 * 4096];
__device__ int g_idx[BB];

// ---------------- threefry2x32 (exact JAX rounds) ----------------
__device__ __forceinline__ uint32_t rotl32(uint32_t x, int d) { return (x << d) | (x >> (32 - d)); }
__device__ __forceinline__ void threefry2x32(uint32_t k0, uint32_t k1, uint32_t x0, uint32_t x1,
                                             uint32_t& o0, uint32_t& o1) {
    uint32_t ks0 = k0, ks1 = k1, ks2 = 0x1BD11BDAu ^ k0 ^ k1;
    x0 += ks0; x1 += ks1;
    x0 += x1; x1 = rotl32(x1, 13); x1 ^= x0;
    x0 += x1; x1 = rotl32(x1, 15); x1 ^= x0;
    x0 += x1; x1 = rotl32(x1, 26); x1 ^= x0;
    x0 += x1; x1 = rotl32(x1,  6); x1 ^= x0;
    x0 += ks1; x1 += ks2 + 1u;
    x0 += x1; x1 = rotl32(x1, 17); x1 ^= x0;
    x0 += x1; x1 = rotl32(x1, 29); x1 ^= x0;
    x0 += x1; x1 = rotl32(x1, 16); x1 ^= x0;
    x0 += x1; x1 = rotl32(x1, 24); x1 ^= x0;
    x0 += ks2; x1 += ks0 + 2u;
    x0 += x1; x1 = rotl32(x1, 13); x1 ^= x0;
    x0 += x1; x1 = rotl32(x1, 15); x1 ^= x0;
    x0 += x1; x1 = rotl32(x1, 26); x1 ^= x0;
    x0 += x1; x1 = rotl32(x1,  6); x1 ^= x0;
    x0 += ks0; x1 += ks1 + 3u;
    x0 += x1; x1 = rotl32(x1, 17); x1 ^= x0;
    x0 += x1; x1 = rotl32(x1, 29); x1 ^= x0;
    x0 += x1; x1 = rotl32(x1, 16); x1 ^= x0;
    x0 += x1; x1 = rotl32(x1, 24); x1 ^= x0;
    x0 += ks1; x1 += ks2 + 4u;
    x0 += x1; x1 = rotl32(x1, 13); x1 ^= x0;
    x0 += x1; x1 = rotl32(x1, 15); x1 ^= x0;
    x0 += x1; x1 = rotl32(x1, 26); x1 ^= x0;
    x0 += x1; x1 = rotl32(x1,  6); x1 ^= x0;
    x0 += ks2; x1 += ks0 + 5u;
    o0 = x0; o1 = x1;
}

// ---------------- PTX helpers (sm_80-level only: works on plain sm_103 target) ----------------
__device__ __forceinline__ uint32_t smem_u32(const void* p) {
    uint32_t a;
    asm("{ .reg .u64 t; cvta.to.shared.u64 t, %1; cvt.u32.u64 %0, t; }" : "=r"(a) : "l"(p));
    return a;
}
__device__ __forceinline__ void ldm_x4(uint32_t* r, uint32_t addr) {
    asm volatile("ldmatrix.sync.aligned.m8n8.x4.shared.b16 {%0,%1,%2,%3}, [%4];"
        : "=r"(r[0]), "=r"(r[1]), "=r"(r[2]), "=r"(r[3]) : "r"(addr));
}
__device__ __forceinline__ void ldm_x2(uint32_t* r, uint32_t addr) {
    asm volatile("ldmatrix.sync.aligned.m8n8.x2.shared.b16 {%0,%1}, [%2];"
        : "=r"(r[0]), "=r"(r[1]) : "r"(addr));
}
__device__ __forceinline__ void mma16816(float* d, const uint32_t* a, const uint32_t* b) {
    asm volatile(
        "mma.sync.aligned.m16n8k16.row.col.f32.bf16.bf16.f32 "
        "{%0,%1,%2,%3}, {%4,%5,%6,%7}, {%8,%9}, {%0,%1,%2,%3};"
        : "+f"(d[0]), "+f"(d[1]), "+f"(d[2]), "+f"(d[3])
        : "r"(a[0]), "r"(a[1]), "r"(a[2]), "r"(a[3]), "r"(b[0]), "r"(b[1]));
}
__device__ __forceinline__ void cpasync16(uint32_t dst, const void* src) {
    asm volatile("cp.async.cg.shared.global [%0], [%1], 16;" :: "r"(dst), "l"(src));
}
#define CP_COMMIT() asm volatile("cp.async.commit_group;" ::: "memory")
#define CP_WAIT1()  asm volatile("cp.async.wait_group 1;" ::: "memory")

// ---------------- Kernel P: convert weights to bf16 hi/lo ----------------
__global__ __launch_bounds__(256) void prep_w_kernel(const float* __restrict__ triz_w) {
    int t = blockIdx.x * 256 + threadIdx.x;
    if (t >= 40 * 4096) return;
    float v = triz_w[t];
    __nv_bfloat16 hi = __float2bfloat16(v);
    __nv_bfloat16 lo = __float2bfloat16(v - __bfloat162float(hi));
    g_whi[t] = hi;
    g_wlo[t] = lo;
}

// ---------------- Kernel A1: encoder + z(bf16 hi/lo) + raw policy logits ----------------
__global__ __launch_bounds__(128) void enc_kernel(
    const float* __restrict__ x, const float* __restrict__ enc_w,
    const float* __restrict__ enc_b, const float* __restrict__ pol_w,
    const float* __restrict__ pol_b, float* __restrict__ logits_out) {
    __shared__ float sew[320], seb[64], spw[2560], spb[40];
    int t = threadIdx.x;
    for (int i = t; i < 320; i += 128) sew[i] = enc_w[i];
    if (t < 64) seb[t] = enc_b[t];
    for (int i = t; i < 2560; i += 128) spw[i] = pol_w[i];
    if (t < 40) spb[t] = pol_b[t];
    __syncthreads();

    int b = blockIdx.x * 128 + t;
    float xv[5];
#pragma unroll
    for (int d = 0; d < 5; ++d) xv[d] = x[b * 5 + d];

    float z[64];
#pragma unroll
    for (int j = 0; j < 64; ++j) {
        float a = seb[j];
#pragma unroll
        for (int d = 0; d < 5; ++d) a = fmaf(xv[d], sew[j * 5 + d], a);
        z[j] = tanhf(a);
    }

    uint4* zh = (uint4*)g_zhi + (size_t)b * 8;
    uint4* zl = (uint4*)g_zlo + (size_t)b * 8;
#pragma unroll
    for (int c = 0; c < 8; ++c) {
        uint32_t hq[4], lq[4];
#pragma unroll
        for (int q = 0; q < 4; ++q) {
            float a = z[c * 8 + 2 * q], d = z[c * 8 + 2 * q + 1];
            __nv_bfloat162 hv = __floats2bfloat162_rn(a, d);
            float2 hf = __bfloat1622float2(hv);
            __nv_bfloat162 lv = __floats2bfloat162_rn(a - hf.x, d - hf.y);
            hq[q] = *(uint32_t*)&hv;
            lq[q] = *(uint32_t*)&lv;
        }
        zh[c] = make_uint4(hq[0], hq[1], hq[2], hq[3]);
        zl[c] = make_uint4(lq[0], lq[1], lq[2], lq[3]);
    }

    float* lo_ = logits_out + (size_t)b * 40;
#pragma unroll 4
    for (int k = 0; k < 40; ++k) {
        float a = spb[k];
#pragma unroll
        for (int d = 0; d < 64; ++d) a = fmaf(z[d], spw[k * 64 + d], a);
        lo_[k] = a;
    }
}

// ---------------- Kernel A2: softmax + gumbel-argmax sample (in-place logits->probs) ----------------
__global__ __launch_bounds__(256) void sample_kernel(float* __restrict__ probs) {
    int b = blockIdx.x * 256 + threadIdx.x;
    float l[40];
    uint4* pp = (uint4*)(probs + (size_t)b * 40);
#pragma unroll
    for (int j = 0; j < 10; ++j) {
        uint4 v = pp[j];
        l[4 * j] = __uint_as_float(v.x); l[4 * j + 1] = __uint_as_float(v.y);
        l[4 * j + 2] = __uint_as_float(v.z); l[4 * j + 3] = __uint_as_float(v.w);
    }
    float m = -3.402823466e38f;
#pragma unroll
    for (int k = 0; k < 40; ++k) m = fmaxf(m, l[k]);
    float sum = 0.f;
#pragma unroll 4
    for (int k = 0; k < 40; ++k) {
        float e = expf(l[k] - m);
        l[k] = e;
        sum += e;
    }
    int best = 0;
    float bestv = -3.402823466e38f;
    const float TINY = 1.17549435e-38f;
#pragma unroll 4
    for (int k = 0; k < 40; ++k) {
        float p = l[k] / sum;
        l[k] = p;
        uint32_t i = (uint32_t)(b * 40 + k);
        uint32_t o0, o1;
        threefry2x32(0u, 1u, 0u, i, o0, o1);
        uint32_t bits = o0 ^ o1;
        float f = __uint_as_float((bits >> 9) | 0x3f800000u) - 1.0f;
        float u = fmaxf(f * (1.0f - TINY) + TINY, TINY);
        float g = -logf(-logf(u));
        float v = logf(p) + g;
        if (v > bestv) { bestv = v; best = k; }
    }
    g_idx[b] = best;
#pragma unroll
    for (int j = 0; j < 10; ++j)
        pp[j] = make_uint4(__float_as_uint(l[4 * j]), __float_as_uint(l[4 * j + 1]),
                           __float_as_uint(l[4 * j + 2]), __float_as_uint(l[4 * j + 3]));
}

// ---------------- Kernel B: TRIZ expert bank via mma.sync bf16 (hi/lo 3-pass) ----------------
// CTA = 256 thr (8 warps) x 128 rows. z hi/lo resident in smem (stride 72 bf16 ->
// conflict-free ldmatrix). W double-buffered via cp.async. Each warp: one m16 tile.
#define ZSTRIDE 72            /* bf16 elems per smem row: 144B, 16B-aligned, conflict-free */
#define ZMAT_B (128 * 144)    /* 18432 B per z matrix */
#define WMAT_B (64 * 144)     /* 9216 B per W matrix */
#define O_ZH 0
#define O_ZL ZMAT_B
#define O_WBUF (2 * ZMAT_B)   /* 4 matrices: buf0 hi, buf0 lo, buf1 hi, buf1 lo */
#define TRIZ_SMEM (O_WBUF + 4 * WMAT_B)

__global__ void __launch_bounds__(256) triz_kernel(
    const float* __restrict__ triz_b, float* __restrict__ h_out) {
    extern __shared__ __align__(128) char sm[];
    uint32_t sb = smem_u32(sm);
    int t = threadIdx.x, wid = t >> 5, lane = t & 31;
    size_t row0 = (size_t)blockIdx.x * 128;

    // prologue: z (hi+lo) + W0 -> group0 ; W1 -> group1
    {
        const uint4* zh = (const uint4*)(g_zhi + row0 * 64);
        const uint4* zl = (const uint4*)(g_zlo + row0 * 64);
#pragma unroll
        for (int i = 0; i < 4; ++i) {
            int c = t + i * 256;                 // chunk 0..1023 (row = c>>3, part = c&7)
            uint32_t dst = sb + (c >> 3) * 144 + (c & 7) * 16;
            cpasync16(dst + O_ZH, zh + c);
            cpasync16(dst + O_ZL, zl + c);
        }
    }
    auto loadW = [&](int k, int p) {           // 512 chunks per matrix, 2 per thread
        const uint4* sh = (const uint4*)(g_whi + (size_t)k * 4096);
        const uint4* sl = (const uint4*)(g_wlo + (size_t)k * 4096);
        uint32_t base = sb + O_WBUF + p * 2 * WMAT_B;
#pragma unroll
        for (int i = 0; i < 2; ++i) {
            int c = t + i * 256;
            uint32_t dst = base + (c >> 3) * 144 + (c & 7) * 16;
            cpasync16(dst, sh + c);
            cpasync16(dst + WMAT_B, sl + c);
        }
    };
    loadW(0, 0);
    CP_COMMIT();
    loadW(1, 1);
    CP_COMMIT();

    CP_WAIT1();                                // z + W0 ready
    __syncthreads();

    // A fragments (loop-invariant): azh[kc][4], azl[kc][4]
    uint32_t azh[4][4], azl[4][4];
    {
        int lr = lane & 7, sel = lane >> 3;
        int row = wid * 16 + ((sel & 1) << 3) + lr;
        int kof = (sel & 2) << 2;              // 0 or 8
        uint32_t base = sb + row * 144 + kof * 2;
#pragma unroll
        for (int kc = 0; kc < 4; ++kc) {
            ldm_x4(azh[kc], base + O_ZH + kc * 32);
            ldm_x4(azl[kc], base + O_ZL + kc * 32);
        }
    }

    int gid = lane >> 2, tig = lane & 3;
    size_t rA = row0 + wid * 16 + gid;         // row for acc[0..1]; rA+8 for acc[2..3]

    for (int k = 0; k < 40; ++k) {
        int p = k & 1;
        if (k > 0) {
            CP_WAIT1();
            __syncthreads();
        }
        uint32_t wh = sb + O_WBUF + p * 2 * WMAT_B;
        uint32_t wl = wh + WMAT_B;
        // B ldmatrix lane addressing (x2): lanes 0-7 k-lo, 8-15 k-hi
        int lr = lane & 7, sel = (lane >> 3) & 1;
        uint32_t boff = (lr)*144 + sel * 16;

#pragma unroll
        for (int nt = 0; nt < 8; ++nt) {
            float2 bv = *(const float2*)(triz_b + k * 64 + nt * 8 + 2 * tig);
            float acc[4] = {bv.x, bv.y, bv.x, bv.y};
            uint32_t nb = nt * 8 * 144 + boff;
#pragma unroll
            for (int kc = 0; kc < 4; ++kc) {
                uint32_t bh[2], bl[2];
                ldm_x2(bh, wh + nb + kc * 32);
                ldm_x2(bl, wl + nb + kc * 32);
                mma16816(acc, azh[kc], bh);
                mma16816(acc, azl[kc], bh);
                mma16816(acc, azh[kc], bl);
            }
            float2 v0 = make_float2(fmaxf(acc[0], 0.f), fmaxf(acc[1], 0.f));
            float2 v1 = make_float2(fmaxf(acc[2], 0.f), fmaxf(acc[3], 0.f));
            *(float2*)(h_out + (rA * 40 + k) * 64 + nt * 8 + 2 * tig) = v0;
            *(float2*)(h_out + ((rA + 8) * 40 + k) * 64 + nt * 8 + 2 * tig) = v1;
        }
        __syncthreads();                       // done reading buf p before refill
        if (k + 2 < 40) loadW(k + 2, p);
        CP_COMMIT();                           // keep group accounting uniform
    }
}

// ---------------- Kernel C: gather selected expert + decoder ----------------
__global__ __launch_bounds__(256) void decode_kernel(
    const float* __restrict__ dec_w, const float* __restrict__ dec_b,
    const float* __restrict__ h, float* __restrict__ out) {
    int b = blockIdx.x * 256 + threadIdx.x;
    int k = g_idx[b];
    const float4* hp = (const float4*)(h + ((size_t)b * 40 + k) * 64);
    float acc[5];
#pragma unroll
    for (int j = 0; j < 5; ++j) acc[j] = dec_b[j];
#pragma unroll
    for (int i = 0; i < 16; ++i) {
        float4 v = hp[i];
        int d = i * 4;
#pragma unroll
        for (int j = 0; j < 5; ++j) {
            acc[j] = fmaf(v.x, dec_w[j * 64 + d],     acc[j]);
            acc[j] = fmaf(v.y, dec_w[j * 64 + d + 1], acc[j]);
            acc[j] = fmaf(v.z, dec_w[j * 64 + d + 2], acc[j]);
            acc[j] = fmaf(v.w, dec_w[j * 64 + d + 3], acc[j]);
        }
    }
#pragma unroll
    for (int j = 0; j < 5; ++j) out[b * 5 + j] = acc[j];
}

// ---------------- launch ----------------
extern "C" void kernel_launch(void* const* d_in, const int* in_sizes, int n_in,
                              void* d_out, int out_size) {
    const float* x      = (const float*)d_in[0];
    const float* enc_w  = (const float*)d_in[1];
    const float* enc_b  = (const float*)d_in[2];
    const float* triz_w = (const float*)d_in[3];
    const float* triz_b = (const float*)d_in[4];
    const float* pol_w  = (const float*)d_in[5];
    const float* pol_b  = (const float*)d_in[6];
    const float* dec_w  = (const float*)d_in[7];
    const float* dec_b  = (const float*)d_in[8];

    float* out   = (float*)d_out;                 // [B,5]
    float* probs = out + (size_t)BB * 5;          // [B,40]
    float* h     = out + (size_t)BB * 45;         // [B,40,64]

    cudaFuncSetAttribute(triz_kernel, cudaFuncAttributeMaxDynamicSharedMemorySize, TRIZ_SMEM);

    prep_w_kernel<<<(40 * 4096 + 255) / 256, 256>>>(triz_w);
    enc_kernel<<<BB / 128, 128>>>(x, enc_w, enc_b, pol_w, pol_b, probs);
    sample_kernel<<<BB / 256, 256>>>(probs);
    triz_kernel<<<BB / 128, 256, TRIZ_SMEM>>>(triz_b, h);
    decode_kernel<<<BB / 256, 256>>>(dec_w, dec_b, h, out);
}